// round 8
// baseline (speedup 1.0000x reference)
#include <cuda_runtime.h>
#include <math.h>

typedef unsigned long long ull;

// Problem constants
#define DHID   1024
#define BATCH  32
#define TSTEPS 513           // GRU steps (U+1)
#define N3     3072
#define NCTA   128           // persistent grid: 8 hidden units per CTA, 1 CTA/SM

// SMEM: Wh slice [24 rows][1024] (96KB) + exchange [16 warps][12 rows][32 b] (24KB)
#define WH_SM_FLOATS (24 * 1024)
#define EXCH_FLOATS  (16 * 12 * 32)
#define STEP_SMEM    ((WH_SM_FLOATS + EXCH_FLOATS) * 4)   // 122880 bytes

// ---------------- f32x2 packed-FMA helpers ----------------
#define FMA2(acc, a, b) asm("fma.rn.f32x2 %0, %1, %2, %0;" : "+l"(acc) : "l"(a), "l"(b))
#define PACKDUP(d, v)   asm("mov.b64 %0, {%1, %1};" : "=l"(d) : "f"(v))
#define UNPK(lo, hi, v) asm("mov.b64 {%0, %1}, %2;" : "=f"(lo), "=f"(hi) : "l"(v))

// ---------------- device scratch (no allocation allowed) ----------------
__device__ float g_Eproj[1024 * N3];                       // embed @ Wx + bx (12.6 MB)
__device__ uint4 g_WhT4[(size_t)N3 * (DHID / 4)];          // Wh^T [3D][D], 16B aligned
__device__ uint4 g_hp4[(size_t)(TSTEPS + 1) * (BATCH * DHID / 4)];  // h packed [s][k4][b][4]
__device__ float g_hf[(size_t)(TSTEPS + 1) * BATCH * DHID];         // h flat   [s][b][k]
__device__ unsigned g_done[(TSTEPS + 1) * NCTA];           // dataflow flags [s][cta]

// ---------------- init: packed h0 broadcast + flag reset ----------------
__global__ void init_kernel(const float* __restrict__ h0) {
    int idx = blockIdx.x * blockDim.x + threadIdx.x;       // 32768 threads
    int k = ((idx >> 7) << 2) | (idx & 3);                 // packed [k4][b][4]
    ((float*)g_hp4)[idx] = h0[k];
    g_done[idx] = 0;
    g_done[idx + 32768] = 0;
    if (idx < (TSTEPS + 1) * NCTA - 65536) g_done[idx + 65536] = 0;
}

// ---------------- transpose Wh [D,3D] -> WhT [3D,D] ----------------
__global__ void transpose_wh_kernel(const float* __restrict__ Wh) {
    __shared__ float t[32][33];
    int j = blockIdx.x * 32 + threadIdx.x;
    int d = blockIdx.y * 32 + threadIdx.y;
    t[threadIdx.y][threadIdx.x] = Wh[(size_t)d * N3 + j];
    __syncthreads();
    int dd = blockIdx.y * 32 + threadIdx.x;
    int jj = blockIdx.x * 32 + threadIdx.y;
    ((float*)g_WhT4)[(size_t)jj * DHID + dd] = t[threadIdx.x][threadIdx.y];
}

// ---------------- packed-fp32 tiled GEMM: C = A[M,K]*B[K,N] + bias ----------------
// mode 0: C[row*N+col]   mode 1: row=t*32+b -> C[(b*513+t)*1024+col]
__global__ __launch_bounds__(256)
void gemm_bias_kernel(const float* __restrict__ A, const float* __restrict__ Bm,
                      const float* __restrict__ bias, float* __restrict__ C,
                      int M, int N, int K, int mode) {
    __shared__ ull   sAd[32][65];
    __shared__ float sB[32][64];
    int bm = blockIdx.y * 64, bn = blockIdx.x * 64;
    int tid = threadIdx.x;
    int tr = tid >> 4, tc = tid & 15;
    ull acc[4][2];
#pragma unroll
    for (int i = 0; i < 4; i++) { acc[i][0] = 0ull; acc[i][1] = 0ull; }

    for (int k0 = 0; k0 < K; k0 += 32) {
#pragma unroll
        for (int i = tid; i < 64 * 32; i += 256) {
            int r = i >> 5, cc = i & 31;
            int gr = bm + r;
            float v = (gr < M) ? A[(size_t)gr * K + k0 + cc] : 0.f;
            ull dv; PACKDUP(dv, v);
            sAd[cc][r] = dv;
        }
#pragma unroll
        for (int i = tid; i < 32 * 64; i += 256) {
            int r = i >> 6, cc = i & 63;
            sB[r][cc] = Bm[(size_t)(k0 + r) * N + bn + cc];
        }
        __syncthreads();
#pragma unroll
        for (int kk = 0; kk < 32; kk++) {
            ull a0 = sAd[kk][tr * 4 + 0];
            ull a1 = sAd[kk][tr * 4 + 1];
            ull a2 = sAd[kk][tr * 4 + 2];
            ull a3 = sAd[kk][tr * 4 + 3];
            ull b0 = *(const ull*)&sB[kk][tc * 4];
            ull b1 = *(const ull*)&sB[kk][tc * 4 + 2];
            FMA2(acc[0][0], a0, b0); FMA2(acc[0][1], a0, b1);
            FMA2(acc[1][0], a1, b0); FMA2(acc[1][1], a1, b1);
            FMA2(acc[2][0], a2, b0); FMA2(acc[2][1], a2, b1);
            FMA2(acc[3][0], a3, b0); FMA2(acc[3][1], a3, b1);
        }
        __syncthreads();
    }
#pragma unroll
    for (int i = 0; i < 4; i++) {
        int row = bm + tr * 4 + i;
        if (row >= M) continue;
#pragma unroll
        for (int j2 = 0; j2 < 2; j2++) {
            float lo, hi; UNPK(lo, hi, acc[i][j2]);
            int c0 = bn + tc * 4 + 2 * j2;
            float v0 = lo + bias[c0];
            float v1 = hi + bias[c0 + 1];
            if (mode == 0) {
                C[(size_t)row * N + c0]     = v0;
                C[(size_t)row * N + c0 + 1] = v1;
            } else {
                int t = row >> 5, b = row & 31;
                size_t o = ((size_t)b * 513 + t) * 1024 + c0;
                C[o]     = v0;
                C[o + 1] = v1;
            }
        }
    }
}

// ---------------- persistent GRU recurrence (dataflow-synced) ----------------
// 128 CTAs x 512 threads (1 CTA/SM). CTA owns units j = bid*8..bid*8+7
// (24 Wh rows resident in SMEM). Warp w = (row-half rh = w&1, k-slice ks = w>>1):
// reduces rows rh*12..+12 over k4 [ks*32, ks*32+32), lane = batch.
// Sync: per-step per-CTA release flags; consumer warps acquire-poll only their
// 16 producer CTAs' flags (no global barrier, no fence, no L1 flush).
// h loads go through L1 (partner warp with same ks hits); prefetch is clamped
// inside the slice so no line of a future step can enter L1 early.
__global__ __launch_bounds__(512, 1)
void gru_persist_kernel(const float* __restrict__ bh, const int* __restrict__ y) {
    extern __shared__ float sm[];
    float* swh = sm;                       // [24][1024]
    float* sex = sm + WH_SM_FLOATS;        // [16 warps][12 rows][32 b]

    const int tid  = threadIdx.x;
    const int lane = tid & 31;
    const int w    = tid >> 5;             // 0..15
    const int rh   = w & 1;                // row half
    const int ks   = w >> 1;               // k-slice 0..7
    const int jbase = blockIdx.x * 8;

    // one-time: load Wh slice into SMEM (row r = u*3+g <- WhT row g*1024+jbase+u)
    for (int i = tid; i < 24 * 256; i += 512) {
        int r = i >> 8, c = i & 255;
        int u = r / 3, g = r - 3 * u;
        ((uint4*)swh)[r * 256 + c] = g_WhT4[(size_t)(g * 1024 + jbase + u) * 256 + c];
    }

    // epilogue constants: thread (unit u=w, batch b=lane), threads 0..255 only
    const bool epi = (tid < 256);
    const int j = epi ? (jbase + w) : jbase;
    float bz = 0.f, br = 0.f, bq = 0.f, hold = 0.f;
    int holdoff = 0;
    if (epi) {
        bz = bh[j]; br = bh[DHID + j]; bq = bh[2 * DHID + j];
        holdoff = ((j >> 2) * 32 + lane) * 4 + (j & 3);    // packed idx of h[b][j]
        hold = __ldcg(((const float*)g_hp4) + holdoff);    // h0
    }
    __syncthreads();

    const float* wbase = swh + (rh * 12) * 1024 + ks * 32 * 4;

    for (int s = 1; s <= TSTEPS; ++s) {
        // prefetch epilogue inputs (independent of h[s-1])
        float ez = 0.f, er = 0.f, eq = 0.f;
        if (epi) {
            int tok = (s == 1) ? 0 : __ldg(&y[lane * 512 + (s - 2)]);
            const float* ep = g_Eproj + (size_t)tok * N3;
            ez = __ldg(ep + j);
            er = __ldg(ep + DHID + j);
            eq = __ldg(ep + 2 * DHID + j);
        }

        // ---- dataflow wait: slice ks of h[s-1] produced by CTAs [ks*16, ks*16+16) ----
        if (s >= 2) {
            if (lane < 16) {
                const unsigned* f = &g_done[(s - 1) * NCTA + ks * 16 + lane];
                unsigned v;
                do {
                    asm volatile("ld.acquire.gpu.global.u32 %0, [%1];"
                                 : "=r"(v) : "l"(f) : "memory");
                } while (!v);
            }
            __syncwarp();
        }

        // ---- main reduction: 32 k4-chunks x 12 rows, lane = batch ----
        ull acc[12];
#pragma unroll
        for (int r = 0; r < 12; r++) acc[r] = 0ull;

        const ulonglong2* __restrict__ hp = ((const ulonglong2*)g_hp4)
            + (size_t)(s - 1) * 8192 + (size_t)(ks * 32) * 32 + lane;

        ulonglong2 h0v = hp[0];
        ulonglong2 h1v = hp[32];
#pragma unroll 4
        for (int kk = 0; kk < 32; kk++) {
            int pf = (kk + 2 <= 31) ? (kk + 2) : 31;   // clamp: never read outside slice
            ulonglong2 h2v = hp[(size_t)pf * 32];
            const float* wb = wbase + kk * 4;
#pragma unroll
            for (int r = 0; r < 12; r++) {
                ulonglong2 wv = *(const ulonglong2*)(wb + r * 1024);
                FMA2(acc[r], wv.x, h0v.x);
                FMA2(acc[r], wv.y, h0v.y);
            }
            h0v = h1v; h1v = h2v;
        }

        // fold f32x2 and publish partials: sex[w][r][lane]
#pragma unroll
        for (int r = 0; r < 12; r++) {
            float lo, hi; UNPK(lo, hi, acc[r]);
            sex[(w * 12 + r) * 32 + lane] = lo + hi;
        }
        __syncthreads();

        // ---- epilogue: thread (u=w, b=lane), tid < 256 ----
        if (epi) {
            float hg[3];
#pragma unroll
            for (int g = 0; g < 3; g++) {
                int rr = w * 3 + g;
                int half = rr >= 12 ? 1 : 0;
                int lr = rr - half * 12;
                float t = 0.f;
#pragma unroll
                for (int k2 = 0; k2 < 8; k2++)
                    t += sex[(((k2 << 1) | half) * 12 + lr) * 32 + lane];
                hg[g] = t;
            }
            float hz = hg[0] + bz, hr = hg[1] + br, hq = hg[2] + bq;
            float zg = __fdividef(1.f, 1.f + __expf(-(ez + hz)));
            float rg = __fdividef(1.f, 1.f + __expf(-(er + hr)));
            float xq = eq + rg * hq;
            float e2 = __expf(2.f * xq);
            float hc = 1.f - __fdividef(2.f, e2 + 1.f);
            float hn = zg * hold + (1.f - zg) * hc;
            hold = hn;                                      // carried in register

            __stcg(((float*)g_hp4) + (size_t)s * 32768 + holdoff, hn);   // packed
            __stcg(&g_hf[(size_t)s * 32768 + (size_t)lane * 1024 + j], hn); // flat
        }

        // ---- publish: this CTA's 8 units of h[s] are ready ----
        __syncthreads();
        if (tid == 0) {
            asm volatile("st.release.gpu.global.u32 [%0], %1;"
                         :: "l"(&g_done[s * NCTA + blockIdx.x]), "r"(1u) : "memory");
        }
    }
}

// ---------------- launch ----------------
extern "C" void kernel_launch(void* const* d_in, const int* in_sizes, int n_in,
                              void* d_out, int out_size) {
    const int*   y   = (const int*)d_in[0];
    const float* emb = (const float*)d_in[1];
    const float* Wx  = (const float*)d_in[2];
    const float* Wh  = (const float*)d_in[3];
    const float* bx  = (const float*)d_in[4];
    const float* bh  = (const float*)d_in[5];
    const float* Wd  = (const float*)d_in[6];
    const float* bd  = (const float*)d_in[7];
    const float* h0  = (const float*)d_in[8];
    float* out = (float*)d_out;

    float *pE, *pHf;
    cudaGetSymbolAddress((void**)&pE, g_Eproj);
    cudaGetSymbolAddress((void**)&pHf, g_hf);

    cudaFuncSetAttribute(gru_persist_kernel,
                         cudaFuncAttributeMaxDynamicSharedMemorySize, STEP_SMEM);

    // init packed h0 + reset dataflow flags (every replay)
    init_kernel<<<32, 1024>>>(h0);
    // WhT = transpose(Wh)
    transpose_wh_kernel<<<dim3(96, 32), dim3(32, 32)>>>(Wh);
    // Eproj = embed_table @ Wx + bx (only 1024 distinct token rows)
    gemm_bias_kernel<<<dim3(48, 16), 256>>>(emb, Wx, bx, pE, 1024, N3, 1024, 0);
    // persistent GRU recurrence (513 steps, one launch, dataflow-synced)
    gru_persist_kernel<<<NCTA, 512, STEP_SMEM>>>(bh, y);
    // outs[b,t,:] = h_{t+1}[b,:] @ Wd + bd
    gemm_bias_kernel<<<dim3(16, 257), 256>>>(pHf + 32768, Wd, bd, out,
                                             TSTEPS * BATCH, 1024, 1024, 1);
}

// round 9
// speedup vs baseline: 1.4740x; 1.4740x over previous
#include <cuda_runtime.h>
#include <math.h>

typedef unsigned long long ull;

// Problem constants
#define DHID   1024
#define BATCH  32
#define TSTEPS 513           // GRU steps (U+1)
#define N3     3072
#define NCTA   128           // persistent grid: 8 hidden units per CTA, 1 CTA/SM

// SMEM: Wh slice [24 rows][1024] (96KB) + exchange [16 warps][12 rows][32 b] (24KB)
#define WH_SM_FLOATS (24 * 1024)
#define EXCH_FLOATS  (16 * 12 * 32)
#define STEP_SMEM    ((WH_SM_FLOATS + EXCH_FLOATS) * 4)   // 122880 bytes

// ---------------- f32x2 packed-FMA helpers ----------------
#define FMA2(acc, a, b) asm("fma.rn.f32x2 %0, %1, %2, %0;" : "+l"(acc) : "l"(a), "l"(b))
#define PACKDUP(d, v)   asm("mov.b64 %0, {%1, %1};" : "=l"(d) : "f"(v))
#define UNPK(lo, hi, v) asm("mov.b64 {%0, %1}, %2;" : "=f"(lo), "=f"(hi) : "l"(v))

// ---------------- device scratch (no allocation allowed) ----------------
__device__ float g_Eproj[1024 * N3];                       // embed @ Wx + bx (12.6 MB)
__device__ uint4 g_WhT4[(size_t)N3 * (DHID / 4)];          // Wh^T [3D][D], 16B aligned
__device__ uint4 g_hp4[(size_t)(TSTEPS + 1) * (BATCH * DHID / 4)];  // h packed [s][k4][b][4]
__device__ float g_hf[(size_t)(TSTEPS + 1) * BATCH * DHID];         // h flat   [s][b][k]
__device__ unsigned g_cnt[TSTEPS + 2];                     // per-step barrier counters

// ---------------- init: packed h0 broadcast + barrier counter reset ----------------
__global__ void init_kernel(const float* __restrict__ h0) {
    int idx = blockIdx.x * blockDim.x + threadIdx.x;       // 32768 threads
    int k = ((idx >> 7) << 2) | (idx & 3);                 // packed [k4][b][4]
    ((float*)g_hp4)[idx] = h0[k];
    if (idx < TSTEPS + 2) g_cnt[idx] = 0;
}

// ---------------- transpose Wh [D,3D] -> WhT [3D,D] ----------------
__global__ void transpose_wh_kernel(const float* __restrict__ Wh) {
    __shared__ float t[32][33];
    int j = blockIdx.x * 32 + threadIdx.x;
    int d = blockIdx.y * 32 + threadIdx.y;
    t[threadIdx.y][threadIdx.x] = Wh[(size_t)d * N3 + j];
    __syncthreads();
    int dd = blockIdx.y * 32 + threadIdx.x;
    int jj = blockIdx.x * 32 + threadIdx.y;
    ((float*)g_WhT4)[(size_t)jj * DHID + dd] = t[threadIdx.x][threadIdx.y];
}

// ---------------- packed-fp32 tiled GEMM: C = A[M,K]*B[K,N] + bias ----------------
// mode 0: C[row*N+col]   mode 1: row=t*32+b -> C[(b*513+t)*1024+col]
__global__ __launch_bounds__(256)
void gemm_bias_kernel(const float* __restrict__ A, const float* __restrict__ Bm,
                      const float* __restrict__ bias, float* __restrict__ C,
                      int M, int N, int K, int mode) {
    __shared__ ull   sAd[32][65];
    __shared__ float sB[32][64];
    int bm = blockIdx.y * 64, bn = blockIdx.x * 64;
    int tid = threadIdx.x;
    int tr = tid >> 4, tc = tid & 15;
    ull acc[4][2];
#pragma unroll
    for (int i = 0; i < 4; i++) { acc[i][0] = 0ull; acc[i][1] = 0ull; }

    for (int k0 = 0; k0 < K; k0 += 32) {
#pragma unroll
        for (int i = tid; i < 64 * 32; i += 256) {
            int r = i >> 5, cc = i & 31;
            int gr = bm + r;
            float v = (gr < M) ? A[(size_t)gr * K + k0 + cc] : 0.f;
            ull dv; PACKDUP(dv, v);
            sAd[cc][r] = dv;
        }
#pragma unroll
        for (int i = tid; i < 32 * 64; i += 256) {
            int r = i >> 6, cc = i & 63;
            sB[r][cc] = Bm[(size_t)(k0 + r) * N + bn + cc];
        }
        __syncthreads();
#pragma unroll
        for (int kk = 0; kk < 32; kk++) {
            ull a0 = sAd[kk][tr * 4 + 0];
            ull a1 = sAd[kk][tr * 4 + 1];
            ull a2 = sAd[kk][tr * 4 + 2];
            ull a3 = sAd[kk][tr * 4 + 3];
            ull b0 = *(const ull*)&sB[kk][tc * 4];
            ull b1 = *(const ull*)&sB[kk][tc * 4 + 2];
            FMA2(acc[0][0], a0, b0); FMA2(acc[0][1], a0, b1);
            FMA2(acc[1][0], a1, b0); FMA2(acc[1][1], a1, b1);
            FMA2(acc[2][0], a2, b0); FMA2(acc[2][1], a2, b1);
            FMA2(acc[3][0], a3, b0); FMA2(acc[3][1], a3, b1);
        }
        __syncthreads();
    }
#pragma unroll
    for (int i = 0; i < 4; i++) {
        int row = bm + tr * 4 + i;
        if (row >= M) continue;
#pragma unroll
        for (int j2 = 0; j2 < 2; j2++) {
            float lo, hi; UNPK(lo, hi, acc[i][j2]);
            int c0 = bn + tc * 4 + 2 * j2;
            float v0 = lo + bias[c0];
            float v1 = hi + bias[c0 + 1];
            if (mode == 0) {
                C[(size_t)row * N + c0]     = v0;
                C[(size_t)row * N + c0 + 1] = v1;
            } else {
                int t = row >> 5, b = row & 31;
                size_t o = ((size_t)b * 513 + t) * 1024 + c0;
                C[o]     = v0;
                C[o + 1] = v1;
            }
        }
    }
}

// ---------------- persistent GRU recurrence ----------------
// 128 CTAs x 512 threads (1 CTA/SM). CTA owns units j = bid*8..bid*8+7
// (24 Wh rows resident in SMEM for the whole launch).
// Warp w = (row-half rh = w&1, slice t = w>>1): reduces rows rh*12..+12 over
// k4 slice ksl = (t + bid) & 7 (32 k4) — the per-CTA rotation spreads the
// post-barrier L2 read burst of h across address space (de-herd).
// Paired warps (rh=0/1, same ksl) share h lines via default-cached LDG (L1 hit
// for the second reader; addresses unique per step so no staleness).
// 16 partials exchanged via SMEM; threads 0..255 run the gate epilogue
// (thread = (unit u=w, batch b=lane)); R6-style global counter barrier.
__global__ __launch_bounds__(512, 1)
void gru_persist_kernel(const float* __restrict__ bh, const int* __restrict__ y) {
    extern __shared__ float sm[];
    float* swh = sm;                       // [24][1024]
    float* sex = sm + WH_SM_FLOATS;        // [16 warps][12 rows][32 b]

    const int tid  = threadIdx.x;
    const int lane = tid & 31;
    const int w    = tid >> 5;             // 0..15
    const int rh   = w & 1;                // row half
    const int ksl  = ((w >> 1) + blockIdx.x) & 7;   // rotated k-slice 0..7
    const int jbase = blockIdx.x * 8;

    // one-time: load Wh slice into SMEM (row r = u*3+g <- WhT row g*1024+jbase+u)
    for (int i = tid; i < 24 * 256; i += 512) {
        int r = i >> 8, c = i & 255;
        int u = r / 3, g = r - 3 * u;
        ((uint4*)swh)[r * 256 + c] = g_WhT4[(size_t)(g * 1024 + jbase + u) * 256 + c];
    }

    // epilogue constants: thread (unit u=w, batch b=lane), threads 0..255 only
    const bool epi = (tid < 256);
    const int j = epi ? (jbase + w) : jbase;
    float bz = 0.f, br = 0.f, bq = 0.f, hold = 0.f;
    int holdoff = 0;
    if (epi) {
        bz = bh[j]; br = bh[DHID + j]; bq = bh[2 * DHID + j];
        holdoff = ((j >> 2) * 32 + lane) * 4 + (j & 3);    // packed idx of h[b][j]
        hold = __ldcg(((const float*)g_hp4) + holdoff);    // h0
    }
    __syncthreads();

    const float* wbase = swh + (rh * 12) * 1024 + ksl * 32 * 4;

    for (int s = 1; s <= TSTEPS; ++s) {
        // prefetch epilogue inputs (independent of h[s-1])
        float ez = 0.f, er = 0.f, eq = 0.f;
        if (epi) {
            int tok = (s == 1) ? 0 : __ldg(&y[lane * 512 + (s - 2)]);
            const float* ep = g_Eproj + (size_t)tok * N3;
            ez = __ldg(ep + j);
            er = __ldg(ep + DHID + j);
            eq = __ldg(ep + 2 * DHID + j);
        }

        // ---- main reduction: 32 k4-chunks x 12 rows, lane = batch ----
        ull acc[12];
#pragma unroll
        for (int r = 0; r < 12; r++) acc[r] = 0ull;

        const ulonglong2* __restrict__ hp = ((const ulonglong2*)g_hp4)
            + (size_t)(s - 1) * 8192 + (size_t)(ksl * 32) * 32 + lane;

        // depth-3 pipeline, clamped inside the slice (no cross-step reads)
        ulonglong2 h0v = hp[0];
        ulonglong2 h1v = hp[32];
        ulonglong2 h2v = hp[64];
#pragma unroll 4
        for (int kk = 0; kk < 32; kk++) {
            int pf = (kk + 3 <= 31) ? (kk + 3) : 31;
            ulonglong2 h3v = hp[(size_t)pf * 32];
            const float* wb = wbase + kk * 4;
#pragma unroll
            for (int r = 0; r < 12; r++) {
                ulonglong2 wv = *(const ulonglong2*)(wb + r * 1024);
                FMA2(acc[r], wv.x, h0v.x);
                FMA2(acc[r], wv.y, h0v.y);
            }
            h0v = h1v; h1v = h2v; h2v = h3v;
        }

        // fold f32x2 and publish partials: sex[w][r][lane]
#pragma unroll
        for (int r = 0; r < 12; r++) {
            float lo, hi; UNPK(lo, hi, acc[r]);
            sex[(w * 12 + r) * 32 + lane] = lo + hi;
        }
        __syncthreads();

        // ---- epilogue: thread (u=w, b=lane), tid < 256 ----
        if (epi) {
            float hg[3];
#pragma unroll
            for (int g = 0; g < 3; g++) {
                int rr = w * 3 + g;
                int half = rr >= 12 ? 1 : 0;
                int lr = rr - half * 12;
                float t = 0.f;
#pragma unroll
                for (int k2 = 0; k2 < 8; k2++)
                    t += sex[(((k2 << 1) | half) * 12 + lr) * 32 + lane];
                hg[g] = t;
            }
            float hz = hg[0] + bz, hr = hg[1] + br, hq = hg[2] + bq;
            float zg = __fdividef(1.f, 1.f + __expf(-(ez + hz)));
            float rg = __fdividef(1.f, 1.f + __expf(-(er + hr)));
            float xq = eq + rg * hq;
            float e2 = __expf(2.f * xq);
            float hc = 1.f - __fdividef(2.f, e2 + 1.f);
            float hn = zg * hold + (1.f - zg) * hc;
            hold = hn;                                      // carried in register

            __stcg(((float*)g_hp4) + (size_t)s * 32768 + holdoff, hn);      // packed
            __stcg(&g_hf[(size_t)s * 32768 + (size_t)lane * 1024 + j], hn); // flat
        }

        // ---- grid barrier (R6-proven: fence + atomic counter + spin) ----
        __syncthreads();
        if (s < TSTEPS) {
            if (tid == 0) {
                __threadfence();
                atomicAdd(&g_cnt[s], 1u);
                while (((volatile unsigned*)g_cnt)[s] < (unsigned)NCTA) { }
            }
            __syncthreads();
        }
    }
}

// ---------------- launch ----------------
extern "C" void kernel_launch(void* const* d_in, const int* in_sizes, int n_in,
                              void* d_out, int out_size) {
    const int*   y   = (const int*)d_in[0];
    const float* emb = (const float*)d_in[1];
    const float* Wx  = (const float*)d_in[2];
    const float* Wh  = (const float*)d_in[3];
    const float* bx  = (const float*)d_in[4];
    const float* bh  = (const float*)d_in[5];
    const float* Wd  = (const float*)d_in[6];
    const float* bd  = (const float*)d_in[7];
    const float* h0  = (const float*)d_in[8];
    float* out = (float*)d_out;

    float *pE, *pHf;
    cudaGetSymbolAddress((void**)&pE, g_Eproj);
    cudaGetSymbolAddress((void**)&pHf, g_hf);

    cudaFuncSetAttribute(gru_persist_kernel,
                         cudaFuncAttributeMaxDynamicSharedMemorySize, STEP_SMEM);

    // init packed h0 + reset barrier counters (every replay)
    init_kernel<<<32, 1024>>>(h0);
    // WhT = transpose(Wh)
    transpose_wh_kernel<<<dim3(96, 32), dim3(32, 32)>>>(Wh);
    // Eproj = embed_table @ Wx + bx (only 1024 distinct token rows)
    gemm_bias_kernel<<<dim3(48, 16), 256>>>(emb, Wx, bx, pE, 1024, N3, 1024, 0);
    // persistent GRU recurrence (513 steps, one launch)
    gru_persist_kernel<<<NCTA, 512, STEP_SMEM>>>(bh, y);
    // outs[b,t,:] = h_{t+1}[b,:] @ Wd + bd
    gemm_bias_kernel<<<dim3(16, 257), 256>>>(pHf + 32768, Wd, bd, out,
                                             TSTEPS * BATCH, 1024, 1024, 1);
}

// round 10
// speedup vs baseline: 1.5873x; 1.0769x over previous
#include <cuda_runtime.h>
#include <math.h>

typedef unsigned long long ull;

// Problem constants
#define DHID   1024
#define BATCH  32
#define TSTEPS 513           // GRU steps (U+1)
#define N3     3072
#define NCTA   128           // persistent grid: 8 hidden units per CTA, 1 CTA/SM

// SMEM: Wh row-pair-packed [1024 k][16 ull] (128KB) + exchange [16 w][24 r][33] (49.5KB)
#define SWH_ULLS   (1024 * 16)
#define SEX_FLOATS (16 * 24 * 33)
#define STEP_SMEM  (SWH_ULLS * 8 + SEX_FLOATS * 4)   // 181760 bytes

// ---------------- f32x2 packed helpers ----------------
#define FMA2(acc, a, b) asm("fma.rn.f32x2 %0, %1, %2, %0;" : "+l"(acc) : "l"(a), "l"(b))
#define PACKDUP(d, v)   asm("mov.b64 %0, {%1, %1};" : "=l"(d) : "f"(v))
#define PACK2(d, lo, hi) asm("mov.b64 %0, {%1, %2};" : "=l"(d) : "f"(lo), "f"(hi))
#define UNPK(lo, hi, v) asm("mov.b64 {%0, %1}, %2;" : "=f"(lo), "=f"(hi) : "l"(v))

// ---------------- device scratch (no allocation allowed) ----------------
__device__ float g_Eproj[1024 * N3];                       // embed @ Wx + bx (12.6 MB)
__device__ uint4 g_WhT4[(size_t)N3 * (DHID / 4)];          // Wh^T [3D][D]
__device__ float g_hb[(size_t)(TSTEPS + 1) * DHID * BATCH]; // h [s][k(=unit j)][b] (67.4 MB)
__device__ unsigned g_cnt[TSTEPS + 2];                     // per-step barrier counters

// ---------------- init: h0 broadcast into g_hb[0] + counter reset ----------------
__global__ void init_kernel(const float* __restrict__ h0) {
    int idx = blockIdx.x * blockDim.x + threadIdx.x;       // 32768 threads
    g_hb[idx] = h0[idx >> 5];                              // [k][b], b = idx&31
    if (idx < TSTEPS + 2) g_cnt[idx] = 0;
}

// ---------------- transpose Wh [D,3D] -> WhT [3D,D] ----------------
__global__ void transpose_wh_kernel(const float* __restrict__ Wh) {
    __shared__ float t[32][33];
    int j = blockIdx.x * 32 + threadIdx.x;
    int d = blockIdx.y * 32 + threadIdx.y;
    t[threadIdx.y][threadIdx.x] = Wh[(size_t)d * N3 + j];
    __syncthreads();
    int dd = blockIdx.y * 32 + threadIdx.x;
    int jj = blockIdx.x * 32 + threadIdx.y;
    ((float*)g_WhT4)[(size_t)jj * DHID + dd] = t[threadIdx.x][threadIdx.y];
}

// ---------------- packed-fp32 tiled GEMM: C = A*B + bias ----------------
// mode 0: A row-major [M,K], C[row*N+col]
// mode 1: A = h in [t][j][b] layout (A base = g_hb + 32768): row gr=(t<<5)|b,
//         element A[gr][j] = Abase[(t*1024 + j)*32 + b]; C[(b*513+t)*1024+col]
__global__ __launch_bounds__(256)
void gemm_bias_kernel(const float* __restrict__ A, const float* __restrict__ Bm,
                      const float* __restrict__ bias, float* __restrict__ C,
                      int M, int N, int K, int mode) {
    __shared__ ull   sAd[32][65];
    __shared__ float sB[32][64];
    int bm = blockIdx.y * 64, bn = blockIdx.x * 64;
    int tid = threadIdx.x;
    int tr = tid >> 4, tc = tid & 15;
    ull acc[4][2];
#pragma unroll
    for (int i = 0; i < 4; i++) { acc[i][0] = 0ull; acc[i][1] = 0ull; }

    for (int k0 = 0; k0 < K; k0 += 32) {
        if (mode == 0) {
#pragma unroll
            for (int i = tid; i < 64 * 32; i += 256) {
                int r = i >> 5, cc = i & 31;
                int gr = bm + r;
                float v = (gr < M) ? A[(size_t)gr * K + k0 + cc] : 0.f;
                ull dv; PACKDUP(dv, v);
                sAd[cc][r] = dv;
            }
        } else {
            // transposing load from g_hb: coalesced along b
#pragma unroll
            for (int i = tid; i < 64 * 32; i += 256) {
                int cc = i >> 6, r = i & 63;
                int gr = bm + r;
                float v = 0.f;
                if (gr < M) {
                    int t = gr >> 5, b = gr & 31;
                    v = A[((size_t)t * 1024 + k0 + cc) * 32 + b];
                }
                ull dv; PACKDUP(dv, v);
                sAd[cc][r] = dv;
            }
        }
#pragma unroll
        for (int i = tid; i < 32 * 64; i += 256) {
            int r = i >> 6, cc = i & 63;
            sB[r][cc] = Bm[(size_t)(k0 + r) * N + bn + cc];
        }
        __syncthreads();
#pragma unroll
        for (int kk = 0; kk < 32; kk++) {
            ull a0 = sAd[kk][tr * 4 + 0];
            ull a1 = sAd[kk][tr * 4 + 1];
            ull a2 = sAd[kk][tr * 4 + 2];
            ull a3 = sAd[kk][tr * 4 + 3];
            ull b0 = *(const ull*)&sB[kk][tc * 4];
            ull b1 = *(const ull*)&sB[kk][tc * 4 + 2];
            FMA2(acc[0][0], a0, b0); FMA2(acc[0][1], a0, b1);
            FMA2(acc[1][0], a1, b0); FMA2(acc[1][1], a1, b1);
            FMA2(acc[2][0], a2, b0); FMA2(acc[2][1], a2, b1);
            FMA2(acc[3][0], a3, b0); FMA2(acc[3][1], a3, b1);
        }
        __syncthreads();
    }
#pragma unroll
    for (int i = 0; i < 4; i++) {
        int row = bm + tr * 4 + i;
        if (row >= M) continue;
#pragma unroll
        for (int j2 = 0; j2 < 2; j2++) {
            float lo, hi; UNPK(lo, hi, acc[i][j2]);
            int c0 = bn + tc * 4 + 2 * j2;
            float v0 = lo + bias[c0];
            float v1 = hi + bias[c0 + 1];
            if (mode == 0) {
                C[(size_t)row * N + c0]     = v0;
                C[(size_t)row * N + c0 + 1] = v1;
            } else {
                int t = row >> 5, b = row & 31;
                size_t o = ((size_t)b * 513 + t) * 1024 + c0;
                C[o]     = v0;
                C[o + 1] = v1;
            }
        }
    }
}

// ---------------- persistent GRU recurrence (distributed-operand) ----------------
// 128 CTAs x 512 threads. CTA owns 24 rows (units jbase..jbase+7, row ru=u*3+g),
// packed as 12 f32x2 row-pairs in SMEM: swh[k][rg*4+p] (rg 0..3, p 0..2, 1 pad).
// Lane = (bg = lane>>2: 4 batches, rg = lane&3: 3 row-pairs). Warp w: k-slice
// [w*64, w*64+64). Per k: 1 LDG.128 of h (one 128B line, 4-way dedup) +
// LDS.128+LDS.64 of Wh (distributed, conflict-free, full crossbar) + 4 dups +
// 12 FMA2. Lane's acc is complete over its slice -> one SMEM exchange ->
// 256-thread gate epilogue -> R6 counter barrier.
__global__ __launch_bounds__(512, 1)
void gru_persist_kernel(const float* __restrict__ bh, const int* __restrict__ y) {
    extern __shared__ ull smu[];
    ull*   swh = smu;                          // [1024][16] ull
    float* sex = (float*)(smu + SWH_ULLS);     // [16][24][33]

    const int tid  = threadIdx.x;
    const int lane = tid & 31;
    const int w    = tid >> 5;                 // 0..15
    const int bg   = lane >> 2;                // 0..7 (4 batches each)
    const int rg   = lane & 3;                 // 0..3 (3 row-pairs each)
    const int jbase = blockIdx.x * 8;

    // one-time: build row-pair-packed Wh in SMEM.
    // pair a (0..11) covers rows ru=2a,2a+1; ru=(u*3+g) -> WhT row g*1024+jbase+u
    const float* WhTf = (const float*)g_WhT4;
    for (int idx = tid; idx < 12 * 1024; idx += 512) {
        int a = idx >> 10, k = idx & 1023;
        int ru0 = 2 * a, ru1 = 2 * a + 1;
        int r0 = (ru0 % 3) * 1024 + jbase + ru0 / 3;
        int r1 = (ru1 % 3) * 1024 + jbase + ru1 / 3;
        float w0 = WhTf[(size_t)r0 * 1024 + k];
        float w1 = WhTf[(size_t)r1 * 1024 + k];
        ull pk; PACK2(pk, w0, w1);
        swh[(size_t)k * 16 + (a / 3) * 4 + (a % 3)] = pk;
    }

    // epilogue constants: thread (u = w, b = lane) for tid < 256
    const bool epi = (tid < 256);
    const int ju = epi ? (jbase + w) : jbase;
    float bz = 0.f, br = 0.f, bq = 0.f, hold = 0.f;
    if (epi) {
        bz = bh[ju]; br = bh[DHID + ju]; bq = bh[2 * DHID + ju];
        hold = __ldg(&((const float*)g_hb)[0]) * 0.f;   // placeholder, set below
        hold = ((const float*)g_hb)[(size_t)ju * 32 + lane]; // = h0[ju]
    }
    __syncthreads();

    const int k0w = w * 64;
    const ull* swk = swh + (size_t)k0w * 16 + rg * 4;

    for (int s = 1; s <= TSTEPS; ++s) {
        // prefetch epilogue inputs (independent of h[s-1])
        float ez = 0.f, er = 0.f, eq = 0.f;
        if (epi) {
            int tok = (s == 1) ? 0 : __ldg(&y[lane * 512 + (s - 2)]);
            const float* ep = g_Eproj + (size_t)tok * N3;
            ez = __ldg(ep + ju);
            er = __ldg(ep + DHID + ju);
            eq = __ldg(ep + 2 * DHID + ju);
        }

        // ---- main reduction: 64 k, 12 row-pairs x 4 batches per lane ----
        ull acc[12];
#pragma unroll
        for (int r = 0; r < 12; r++) acc[r] = 0ull;

        const float* hbase = g_hb + ((size_t)(s - 1) * 1024 + k0w) * 32 + bg * 4;

        uint4 hpre[4];
#pragma unroll
        for (int i = 0; i < 4; i++)
            hpre[i] = __ldcg((const uint4*)(hbase + i * 32));

#pragma unroll 8
        for (int kk = 0; kk < 64; kk++) {
            uint4 hc = hpre[kk & 3];
            int pf = (kk + 4 <= 63) ? (kk + 4) : 63;     // clamp inside slice
            hpre[kk & 3] = __ldcg((const uint4*)(hbase + (size_t)pf * 32));

            const ull* wk = swk + (size_t)kk * 16;
            ulonglong2 wv01 = *(const ulonglong2*)wk;
            ull wv2 = wk[2];

            ull hd0, hd1, hd2, hd3;
            PACKDUP(hd0, __uint_as_float(hc.x));
            PACKDUP(hd1, __uint_as_float(hc.y));
            PACKDUP(hd2, __uint_as_float(hc.z));
            PACKDUP(hd3, __uint_as_float(hc.w));

            FMA2(acc[0], wv01.x, hd0); FMA2(acc[1], wv01.x, hd1);
            FMA2(acc[2], wv01.x, hd2); FMA2(acc[3], wv01.x, hd3);
            FMA2(acc[4], wv01.y, hd0); FMA2(acc[5], wv01.y, hd1);
            FMA2(acc[6], wv01.y, hd2); FMA2(acc[7], wv01.y, hd3);
            FMA2(acc[8],  wv2,   hd0); FMA2(acc[9],  wv2,   hd1);
            FMA2(acc[10], wv2,   hd2); FMA2(acc[11], wv2,   hd3);
        }

        // exchange: unpack row-pairs, store floats sex[w][ru][b]
#pragma unroll
        for (int p = 0; p < 3; p++) {
#pragma unroll
            for (int bb = 0; bb < 4; bb++) {
                float lo, hi; UNPK(lo, hi, acc[p * 4 + bb]);
                int ru = (rg * 3 + p) * 2;
                int b  = bg * 4 + bb;
                sex[(w * 24 + ru)     * 33 + b] = lo;
                sex[(w * 24 + ru + 1) * 33 + b] = hi;
            }
        }
        __syncthreads();

        // ---- epilogue: thread (u=w, b=lane), tid < 256 ----
        if (epi) {
            float hz = bz, hr = br, hqv = bq;
#pragma unroll
            for (int w2 = 0; w2 < 16; w2++) {
                int base = (w2 * 24 + w * 3) * 33 + lane;
                hz  += sex[base];
                hr  += sex[base + 33];
                hqv += sex[base + 66];
            }
            float zg = __fdividef(1.f, 1.f + __expf(-(ez + hz)));
            float rg2 = __fdividef(1.f, 1.f + __expf(-(er + hr)));
            float xq = eq + rg2 * hqv;
            float e2 = __expf(2.f * xq);
            float hc = 1.f - __fdividef(2.f, e2 + 1.f);
            float hn = zg * hold + (1.f - zg) * hc;
            hold = hn;

            __stcg(&g_hb[((size_t)s * 1024 + ju) * 32 + lane], hn);
        }

        // ---- grid barrier (R6-proven: fence + atomic counter + spin) ----
        __syncthreads();
        if (s < TSTEPS) {
            if (tid == 0) {
                __threadfence();
                atomicAdd(&g_cnt[s], 1u);
                while (((volatile unsigned*)g_cnt)[s] < (unsigned)NCTA) { }
            }
            __syncthreads();
        }
    }
}

// ---------------- launch ----------------
extern "C" void kernel_launch(void* const* d_in, const int* in_sizes, int n_in,
                              void* d_out, int out_size) {
    const int*   y   = (const int*)d_in[0];
    const float* emb = (const float*)d_in[1];
    const float* Wx  = (const float*)d_in[2];
    const float* Wh  = (const float*)d_in[3];
    const float* bx  = (const float*)d_in[4];
    const float* bh  = (const float*)d_in[5];
    const float* Wd  = (const float*)d_in[6];
    const float* bd  = (const float*)d_in[7];
    const float* h0  = (const float*)d_in[8];
    float* out = (float*)d_out;

    float *pE, *pHb;
    cudaGetSymbolAddress((void**)&pE, g_Eproj);
    cudaGetSymbolAddress((void**)&pHb, g_hb);

    cudaFuncSetAttribute(gru_persist_kernel,
                         cudaFuncAttributeMaxDynamicSharedMemorySize, STEP_SMEM);

    // init h0 into g_hb[0] + reset barrier counters (every replay)
    init_kernel<<<32, 1024>>>(h0);
    // WhT = transpose(Wh)
    transpose_wh_kernel<<<dim3(96, 32), dim3(32, 32)>>>(Wh);
    // Eproj = embed_table @ Wx + bx (only 1024 distinct token rows)
    gemm_bias_kernel<<<dim3(48, 16), 256>>>(emb, Wx, bx, pE, 1024, N3, 1024, 0);
    // persistent GRU recurrence (513 steps, one launch)
    gru_persist_kernel<<<NCTA, 512, STEP_SMEM>>>(bh, y);
    // outs[b,t,:] = h_{t+1}[b,:] @ Wd + bd  (A read transposed from g_hb, s>=1)
    gemm_bias_kernel<<<dim3(16, 257), 256>>>(pHb + 32768, Wd, bd, out,
                                             TSTEPS * BATCH, 1024, 1024, 1);
}

// round 11
// speedup vs baseline: 1.5931x; 1.0036x over previous
#include <cuda_runtime.h>
#include <math.h>

typedef unsigned long long ull;

// Problem constants
#define DHID   1024
#define BATCH  32
#define TSTEPS 513           // GRU steps (U+1)
#define N3     3072
#define NCTA   128           // persistent grid: 8 hidden units per CTA, 1 CTA/SM

// SMEM: Wh row-pair-packed [1024 k][16 ull] (128KB) + exchange [16 w][24 r][33] (49.5KB)
#define SWH_ULLS   (1024 * 16)
#define SEX_FLOATS (16 * 24 * 33)
#define STEP_SMEM  (SWH_ULLS * 8 + SEX_FLOATS * 4)   // 181760 bytes

// ---------------- f32x2 packed helpers ----------------
#define FMA2(acc, a, b) asm("fma.rn.f32x2 %0, %1, %2, %0;" : "+l"(acc) : "l"(a), "l"(b))
#define PACKDUP(d, v)   asm("mov.b64 %0, {%1, %1};" : "=l"(d) : "f"(v))
#define PACK2(d, lo, hi) asm("mov.b64 %0, {%1, %2};" : "=l"(d) : "f"(lo), "f"(hi))
#define UNPK(lo, hi, v) asm("mov.b64 {%0, %1}, %2;" : "=f"(lo), "=f"(hi) : "l"(v))

// ---------------- device scratch (no allocation allowed) ----------------
__device__ float g_Eproj[1024 * N3];                       // embed @ Wx + bx (12.6 MB)
__device__ uint4 g_WhT4[(size_t)N3 * (DHID / 4)];          // Wh^T [3D][D]
__device__ float g_hb[(size_t)(TSTEPS + 1) * DHID * BATCH]; // h [s][k(=unit j)][b] (67.4 MB)
__device__ unsigned g_cnt[TSTEPS + 2];                     // per-step barrier counters

// ---------------- init: h0 broadcast into g_hb[0] + counter reset ----------------
__global__ void init_kernel(const float* __restrict__ h0) {
    int idx = blockIdx.x * blockDim.x + threadIdx.x;       // 32768 threads
    g_hb[idx] = h0[idx >> 5];                              // [k][b], b = idx&31
    if (idx < TSTEPS + 2) g_cnt[idx] = 0;
}

// ---------------- transpose Wh [D,3D] -> WhT [3D,D] ----------------
__global__ void transpose_wh_kernel(const float* __restrict__ Wh) {
    __shared__ float t[32][33];
    int j = blockIdx.x * 32 + threadIdx.x;
    int d = blockIdx.y * 32 + threadIdx.y;
    t[threadIdx.y][threadIdx.x] = Wh[(size_t)d * N3 + j];
    __syncthreads();
    int dd = blockIdx.y * 32 + threadIdx.x;
    int jj = blockIdx.x * 32 + threadIdx.y;
    ((float*)g_WhT4)[(size_t)jj * DHID + dd] = t[threadIdx.x][threadIdx.y];
}

// ---------------- packed-fp32 tiled GEMM: C = A*B + bias ----------------
// mode 0: A row-major [M,K], C[row*N+col]
// mode 1: A = h in [t][j][b] layout (A base = g_hb + 32768): row gr=(t<<5)|b,
//         element A[gr][j] = Abase[(t*1024 + j)*32 + b]; C[(b*513+t)*1024+col]
__global__ __launch_bounds__(256)
void gemm_bias_kernel(const float* __restrict__ A, const float* __restrict__ Bm,
                      const float* __restrict__ bias, float* __restrict__ C,
                      int M, int N, int K, int mode) {
    __shared__ ull   sAd[32][65];
    __shared__ float sB[32][64];
    int bm = blockIdx.y * 64, bn = blockIdx.x * 64;
    int tid = threadIdx.x;
    int tr = tid >> 4, tc = tid & 15;
    ull acc[4][2];
#pragma unroll
    for (int i = 0; i < 4; i++) { acc[i][0] = 0ull; acc[i][1] = 0ull; }

    for (int k0 = 0; k0 < K; k0 += 32) {
        if (mode == 0) {
#pragma unroll
            for (int i = tid; i < 64 * 32; i += 256) {
                int r = i >> 5, cc = i & 31;
                int gr = bm + r;
                float v = (gr < M) ? A[(size_t)gr * K + k0 + cc] : 0.f;
                ull dv; PACKDUP(dv, v);
                sAd[cc][r] = dv;
            }
        } else {
            // transposing load from g_hb: coalesced along b
#pragma unroll
            for (int i = tid; i < 64 * 32; i += 256) {
                int cc = i >> 6, r = i & 63;
                int gr = bm + r;
                float v = 0.f;
                if (gr < M) {
                    int t = gr >> 5, b = gr & 31;
                    v = A[((size_t)t * 1024 + k0 + cc) * 32 + b];
                }
                ull dv; PACKDUP(dv, v);
                sAd[cc][r] = dv;
            }
        }
#pragma unroll
        for (int i = tid; i < 32 * 64; i += 256) {
            int r = i >> 6, cc = i & 63;
            sB[r][cc] = Bm[(size_t)(k0 + r) * N + bn + cc];
        }
        __syncthreads();
#pragma unroll
        for (int kk = 0; kk < 32; kk++) {
            ull a0 = sAd[kk][tr * 4 + 0];
            ull a1 = sAd[kk][tr * 4 + 1];
            ull a2 = sAd[kk][tr * 4 + 2];
            ull a3 = sAd[kk][tr * 4 + 3];
            ull b0 = *(const ull*)&sB[kk][tc * 4];
            ull b1 = *(const ull*)&sB[kk][tc * 4 + 2];
            FMA2(acc[0][0], a0, b0); FMA2(acc[0][1], a0, b1);
            FMA2(acc[1][0], a1, b0); FMA2(acc[1][1], a1, b1);
            FMA2(acc[2][0], a2, b0); FMA2(acc[2][1], a2, b1);
            FMA2(acc[3][0], a3, b0); FMA2(acc[3][1], a3, b1);
        }
        __syncthreads();
    }
#pragma unroll
    for (int i = 0; i < 4; i++) {
        int row = bm + tr * 4 + i;
        if (row >= M) continue;
#pragma unroll
        for (int j2 = 0; j2 < 2; j2++) {
            float lo, hi; UNPK(lo, hi, acc[i][j2]);
            int c0 = bn + tc * 4 + 2 * j2;
            float v0 = lo + bias[c0];
            float v1 = hi + bias[c0 + 1];
            if (mode == 0) {
                C[(size_t)row * N + c0]     = v0;
                C[(size_t)row * N + c0 + 1] = v1;
            } else {
                int t = row >> 5, b = row & 31;
                size_t o = ((size_t)b * 513 + t) * 1024 + c0;
                C[o]     = v0;
                C[o + 1] = v1;
            }
        }
    }
}

// ---------------- persistent GRU recurrence (distributed-operand, MLP=8) ----------------
// 128 CTAs x 512 threads. CTA owns 24 rows (units jbase..jbase+7, row ru=u*3+g),
// packed as 12 f32x2 row-pairs in SMEM: swh[k][rg*4+p] (rg 0..3, p 0..2, 1 pad).
// Lane = (bg = lane>>2: 4 batches, rg = lane&3: 3 row-pairs). Warp w: k-slice
// [w*64, w*64+64). Per k: 1 LDG.128 of h (one 128B line, depth-8 prefetch) +
// LDS.128+LDS.64 of Wh (distributed, conflict-free) + 4 dups + 12 FMA2.
// One SMEM exchange -> 256-thread gate epilogue -> fence-free release/acquire
// single-counter grid barrier (no CCTL.IVALL: L1 stays warm for Eproj/y).
__global__ __launch_bounds__(512, 1)
void gru_persist_kernel(const float* __restrict__ bh, const int* __restrict__ y) {
    extern __shared__ ull smu[];
    ull*   swh = smu;                          // [1024][16] ull
    float* sex = (float*)(smu + SWH_ULLS);     // [16][24][33]

    const int tid  = threadIdx.x;
    const int lane = tid & 31;
    const int w    = tid >> 5;                 // 0..15
    const int bg   = lane >> 2;                // 0..7 (4 batches each)
    const int rg   = lane & 3;                 // 0..3 (3 row-pairs each)
    const int jbase = blockIdx.x * 8;

    // one-time: build row-pair-packed Wh in SMEM.
    // pair a (0..11) covers rows ru=2a,2a+1; ru=(u*3+g) -> WhT row g*1024+jbase+u
    const float* WhTf = (const float*)g_WhT4;
    for (int idx = tid; idx < 12 * 1024; idx += 512) {
        int a = idx >> 10, k = idx & 1023;
        int ru0 = 2 * a, ru1 = 2 * a + 1;
        int r0 = (ru0 % 3) * 1024 + jbase + ru0 / 3;
        int r1 = (ru1 % 3) * 1024 + jbase + ru1 / 3;
        float w0 = WhTf[(size_t)r0 * 1024 + k];
        float w1 = WhTf[(size_t)r1 * 1024 + k];
        ull pk; PACK2(pk, w0, w1);
        swh[(size_t)k * 16 + (a / 3) * 4 + (a % 3)] = pk;
    }

    // epilogue constants: thread (u = w, b = lane) for tid < 256
    const bool epi = (tid < 256);
    const int ju = epi ? (jbase + w) : jbase;
    float bz = 0.f, br = 0.f, bq = 0.f, hold = 0.f;
    if (epi) {
        bz = bh[ju]; br = bh[DHID + ju]; bq = bh[2 * DHID + ju];
        hold = ((const float*)g_hb)[(size_t)ju * 32 + lane];   // = h0[ju]
    }
    __syncthreads();

    const int k0w = w * 64;
    const ull* swk = swh + (size_t)k0w * 16 + rg * 4;

    for (int s = 1; s <= TSTEPS; ++s) {
        // prefetch epilogue inputs (independent of h[s-1])
        float ez = 0.f, er = 0.f, eq = 0.f;
        if (epi) {
            int tok = (s == 1) ? 0 : __ldg(&y[lane * 512 + (s - 2)]);
            const float* ep = g_Eproj + (size_t)tok * N3;
            ez = __ldg(ep + ju);
            er = __ldg(ep + DHID + ju);
            eq = __ldg(ep + 2 * DHID + ju);
        }

        // ---- main reduction: 64 k, 12 row-pairs x 4 batches per lane ----
        ull acc[12];
#pragma unroll
        for (int r = 0; r < 12; r++) acc[r] = 0ull;

        const float* hbase = g_hb + ((size_t)(s - 1) * 1024 + k0w) * 32 + bg * 4;

        // depth-8 prefetch pipeline (MLP=8 to cover post-barrier L2 latency)
        uint4 hpre[8];
#pragma unroll
        for (int i = 0; i < 8; i++)
            hpre[i] = __ldcg((const uint4*)(hbase + (size_t)i * 32));

#pragma unroll 8
        for (int kk = 0; kk < 64; kk++) {
            uint4 hc = hpre[kk & 7];
            int pf = (kk + 8 <= 63) ? (kk + 8) : 63;     // clamp inside slice
            hpre[kk & 7] = __ldcg((const uint4*)(hbase + (size_t)pf * 32));

            const ull* wk = swk + (size_t)kk * 16;
            ulonglong2 wv01 = *(const ulonglong2*)wk;
            ull wv2 = wk[2];

            ull hd0, hd1, hd2, hd3;
            PACKDUP(hd0, __uint_as_float(hc.x));
            PACKDUP(hd1, __uint_as_float(hc.y));
            PACKDUP(hd2, __uint_as_float(hc.z));
            PACKDUP(hd3, __uint_as_float(hc.w));

            FMA2(acc[0], wv01.x, hd0); FMA2(acc[1], wv01.x, hd1);
            FMA2(acc[2], wv01.x, hd2); FMA2(acc[3], wv01.x, hd3);
            FMA2(acc[4], wv01.y, hd0); FMA2(acc[5], wv01.y, hd1);
            FMA2(acc[6], wv01.y, hd2); FMA2(acc[7], wv01.y, hd3);
            FMA2(acc[8],  wv2,   hd0); FMA2(acc[9],  wv2,   hd1);
            FMA2(acc[10], wv2,   hd2); FMA2(acc[11], wv2,   hd3);
        }

        // exchange: unpack row-pairs, store floats sex[w][ru][b]
#pragma unroll
        for (int p = 0; p < 3; p++) {
#pragma unroll
            for (int bb = 0; bb < 4; bb++) {
                float lo, hi; UNPK(lo, hi, acc[p * 4 + bb]);
                int ru = (rg * 3 + p) * 2;
                int b  = bg * 4 + bb;
                sex[(w * 24 + ru)     * 33 + b] = lo;
                sex[(w * 24 + ru + 1) * 33 + b] = hi;
            }
        }
        __syncthreads();

        // ---- epilogue: thread (u=w, b=lane), tid < 256 ----
        if (epi) {
            float hz = bz, hr = br, hqv = bq;
#pragma unroll
            for (int w2 = 0; w2 < 16; w2++) {
                int base = (w2 * 24 + w * 3) * 33 + lane;
                hz  += sex[base];
                hr  += sex[base + 33];
                hqv += sex[base + 66];
            }
            float zg = __fdividef(1.f, 1.f + __expf(-(ez + hz)));
            float rg2 = __fdividef(1.f, 1.f + __expf(-(er + hr)));
            float xq = eq + rg2 * hqv;
            float e2 = __expf(2.f * xq);
            float hc = 1.f - __fdividef(2.f, e2 + 1.f);
            float hn = zg * hold + (1.f - zg) * hc;
            hold = hn;

            __stcg(&g_hb[((size_t)s * 1024 + ju) * 32 + lane], hn);
        }

        // ---- fence-free grid barrier (release arrive / acquire spin, tid0 only) ----
        __syncthreads();
        if (s < TSTEPS) {
            if (tid == 0) {
                asm volatile("red.release.gpu.global.add.u32 [%0], %1;"
                             :: "l"(&g_cnt[s]), "r"(1u) : "memory");
                unsigned v;
                do {
                    asm volatile("ld.acquire.gpu.global.u32 %0, [%1];"
                                 : "=r"(v) : "l"(&g_cnt[s]) : "memory");
                } while (v < (unsigned)NCTA);
            }
            __syncthreads();
        }
    }
}

// ---------------- launch ----------------
extern "C" void kernel_launch(void* const* d_in, const int* in_sizes, int n_in,
                              void* d_out, int out_size) {
    const int*   y   = (const int*)d_in[0];
    const float* emb = (const float*)d_in[1];
    const float* Wx  = (const float*)d_in[2];
    const float* Wh  = (const float*)d_in[3];
    const float* bx  = (const float*)d_in[4];
    const float* bh  = (const float*)d_in[5];
    const float* Wd  = (const float*)d_in[6];
    const float* bd  = (const float*)d_in[7];
    const float* h0  = (const float*)d_in[8];
    float* out = (float*)d_out;

    float *pE, *pHb;
    cudaGetSymbolAddress((void**)&pE, g_Eproj);
    cudaGetSymbolAddress((void**)&pHb, g_hb);

    cudaFuncSetAttribute(gru_persist_kernel,
                         cudaFuncAttributeMaxDynamicSharedMemorySize, STEP_SMEM);

    // init h0 into g_hb[0] + reset barrier counters (every replay)
    init_kernel<<<32, 1024>>>(h0);
    // WhT = transpose(Wh)
    transpose_wh_kernel<<<dim3(96, 32), dim3(32, 32)>>>(Wh);
    // Eproj = embed_table @ Wx + bx (only 1024 distinct token rows)
    gemm_bias_kernel<<<dim3(48, 16), 256>>>(emb, Wx, bx, pE, 1024, N3, 1024, 0);
    // persistent GRU recurrence (513 steps, one launch)
    gru_persist_kernel<<<NCTA, 512, STEP_SMEM>>>(bh, y);
    // outs[b,t,:] = h_{t+1}[b,:] @ Wd + bd  (A read transposed from g_hb, s>=1)
    gemm_bias_kernel<<<dim3(16, 257), 256>>>(pHb + 32768, Wd, bd, out,
                                             TSTEPS * BATCH, 1024, 1024, 1);
}